// round 4
// baseline (speedup 1.0000x reference)
#include <cuda_runtime.h>
#include <cstdint>

// Fixed problem shape: N_TOT = 8192 + 8192*4000 = 32,776,192 elements.
#define N_CAP 32776192LL

// Scratch: inverse-permuted values. Fully overwritten each launch.
__device__ float g_pv[N_CAP];
__device__ float g_sum;

// ---------------------------------------------------------------------------
__global__ void zero_sum_kernel() { g_sum = 0.0f; }

// ---------------------------------------------------------------------------
// Scatter: g_pv[index[i]] = predict_val[i].  index is INT32 (JAX x64 disabled).
// 4 elements per thread via float4 + int4 vector loads.
__global__ void scatter4_kernel(const float4* __restrict__ val4,
                                const int4* __restrict__ idx4,
                                long long n4, long long n_tot) {
    long long t = (long long)blockIdx.x * blockDim.x + threadIdx.x;
    if (t >= n4) return;
    float4 v = val4[t];
    int4 i = idx4[t];
    // Defensive bounds predicate (free under memory latency).
    if ((unsigned)i.x < (unsigned long long)n_tot) g_pv[i.x] = v.x;
    if ((unsigned)i.y < (unsigned long long)n_tot) g_pv[i.y] = v.y;
    if ((unsigned)i.z < (unsigned long long)n_tot) g_pv[i.z] = v.z;
    if ((unsigned)i.w < (unsigned long long)n_tot) g_pv[i.w] = v.w;
}

// Tail scatter (not hit for this shape; safety for n_tot % 4 != 0).
__global__ void scatter_tail_kernel(const float* __restrict__ val,
                                    const int* __restrict__ idx,
                                    long long start, long long n_tot) {
    long long i = start + (long long)blockIdx.x * blockDim.x + threadIdx.x;
    if (i >= n_tot) return;
    int j = idx[i];
    if ((unsigned)j < (unsigned long long)n_tot) g_pv[j] = val[i];
}

// ---------------------------------------------------------------------------
// Rank + MRR: one warp per positive sample.
// Row p: pos = g_pv[p], negatives at g_pv[num_pos + p*num .. +num).
// Row start is 128B-aligned (num_pos*4 = 32768B, num*4 = 16000B = 125*128B).
__global__ void mrr_kernel(float* __restrict__ out, int num, int num_pos) {
    int gwarp = (int)((blockIdx.x * blockDim.x + threadIdx.x) >> 5);
    int lane  = threadIdx.x & 31;
    if (gwarp >= num_pos) return;

    float posv = g_pv[gwarp];
    const float* __restrict__ row = g_pv + (long long)num_pos + (long long)gwarp * num;

    int cnt = 0;
    #pragma unroll 4
    for (int k = lane; k < num; k += 32)
        cnt += (row[k] > posv) ? 1 : 0;

    cnt = __reduce_add_sync(0xFFFFFFFFu, cnt);

    if (lane == 0) {
        float smrr = 1.0f / (float)(1 + cnt);
        out[1 + gwarp] = smrr;          // sample_mrr
        atomicAdd(&g_sum, smrr);        // mean accumulator (8192 atomics total)
    }
}

// ---------------------------------------------------------------------------
__global__ void finalize_kernel(float* __restrict__ out, int num_pos) {
    out[0] = g_sum / (float)num_pos;   // mrr
}

// ---------------------------------------------------------------------------
extern "C" void kernel_launch(void* const* d_in, const int* in_sizes, int n_in,
                              void* d_out, int out_size) {
    const float* val = (const float*)d_in[0];
    const int*   idx = (const int*)d_in[1];   // int32: JAX x64 is disabled
    float* out = (float*)d_out;

    long long n_tot = (long long)in_sizes[0];
    if (n_tot > N_CAP) n_tot = N_CAP;

    // out = [mrr, sample_mrr(num_pos)]  =>  num_pos = out_size - 1
    int num_pos = out_size - 1;
    if (num_pos < 1) num_pos = 1;
    int num = (int)(n_tot / num_pos) - 1;
    if (num < 0) num = 0;

    // Phase 0: zero accumulator
    zero_sum_kernel<<<1, 1>>>();

    // Phase 1: scatter inverse permutation
    long long n4 = n_tot / 4;
    if (n4 > 0) {
        int threads = 256;
        long long blocks = (n4 + threads - 1) / threads;
        scatter4_kernel<<<(unsigned)blocks, threads>>>(
            (const float4*)val, (const int4*)idx, n4, n_tot);
    }
    long long rem_start = n4 * 4;
    if (rem_start < n_tot) {
        long long rem = n_tot - rem_start;
        scatter_tail_kernel<<<(unsigned)((rem + 255) / 256), 256>>>(
            val, idx, rem_start, n_tot);
    }

    // Phase 2: per-row rank counts (one warp per row, 8 warps per block)
    {
        int threads = 256;
        int warps_per_block = threads / 32;
        int blocks = (num_pos + warps_per_block - 1) / warps_per_block;
        mrr_kernel<<<blocks, threads>>>(out, num, num_pos);
    }

    // Phase 3: mean
    finalize_kernel<<<1, 1>>>(out, num_pos);
}

// round 5
// speedup vs baseline: 2.0951x; 2.0951x over previous
#include <cuda_runtime.h>
#include <cstdint>

// Fixed problem shape: num_pos = 8192, num = 4000, N_TOT = 32,776,192.
#define POS_CAP 16384  // safety cap for pos/cnt tables

__device__ float g_pos[POS_CAP];   // pos[j] values (32KB live)
__device__ int   g_cnt[POS_CAP];   // per-row exceed counters

// ---------------------------------------------------------------------------
// Pass A: stream index (int32). Where j < num_pos, fetch val[i] and store
// pos[j]. Also zero the counters. Only 131MB of idx traffic; val touched for
// ~8192 random elements (≈1MB of lines).
__global__ void passA_kernel(const float* __restrict__ val,
                             const int4* __restrict__ idx4,
                             long long n4, long long n_tot, int num_pos) {
    long long t = (long long)blockIdx.x * blockDim.x + threadIdx.x;

    if (t < num_pos) g_cnt[t] = 0;

    if (t < n4) {
        int4 ii = idx4[t];
        long long base = 4 * t;
        if (ii.x < num_pos && ii.x >= 0) g_pos[ii.x] = val[base + 0];
        if (ii.y < num_pos && ii.y >= 0) g_pos[ii.y] = val[base + 1];
        if (ii.z < num_pos && ii.z >= 0) g_pos[ii.z] = val[base + 2];
        if (ii.w < num_pos && ii.w >= 0) g_pos[ii.w] = val[base + 3];
    }

    // Scalar tail (not hit for this shape).
    if (t == 0) {
        for (long long i = 4 * n4; i < n_tot; i++) {
            const int* idx = (const int*)idx4;
            int j = idx[i];
            if (j >= 0 && j < num_pos) g_pos[j] = val[i];
        }
    }
}

// ---------------------------------------------------------------------------
// Pass B: stream val+idx. For negatives, p = (j - num_pos) * M >> 42 (magic
// div by num), compare against smem-cached pos[p], predicated global REDG.
__global__ void passB_kernel(const float4* __restrict__ val4,
                             const int4* __restrict__ idx4,
                             long long n4, long long n_tot,
                             int num_pos, unsigned long long M) {
    extern __shared__ float s_pos[];
    for (int k = threadIdx.x; k < num_pos; k += blockDim.x)
        s_pos[k] = g_pos[k];
    __syncthreads();

    long long stride = (long long)gridDim.x * blockDim.x;
    for (long long t = (long long)blockIdx.x * blockDim.x + threadIdx.x;
         t < n4; t += stride) {
        float4 v = val4[t];
        int4  ii = idx4[t];

        #define PROC(JJ, VV)                                               \
        {                                                                  \
            unsigned d = (unsigned)((JJ) - num_pos);                       \
            if ((int)(JJ) >= num_pos) {                                    \
                unsigned p = (unsigned)(((unsigned long long)d * M) >> 42);\
                if ((VV) > s_pos[p]) atomicAdd(&g_cnt[p], 1);              \
            }                                                              \
        }
        PROC(ii.x, v.x)
        PROC(ii.y, v.y)
        PROC(ii.z, v.z)
        PROC(ii.w, v.w)
        #undef PROC
    }

    // Scalar tail (not hit for this shape).
    if (blockIdx.x == 0 && threadIdx.x == 0) {
        const float* val = (const float*)val4;
        const int*   idx = (const int*)idx4;
        for (long long i = 4 * n4; i < n_tot; i++) {
            int j = idx[i];
            if (j >= num_pos) {
                unsigned p = (unsigned)(((unsigned long long)(j - num_pos) * M) >> 42);
                if (val[i] > s_pos[p]) atomicAdd(&g_cnt[p], 1);
            }
        }
    }
}

// ---------------------------------------------------------------------------
// Finalize: smrr = 1/(1+cnt), out[0] = mean, out[1..] = smrr. One block.
__global__ void finalize_kernel(float* __restrict__ out, int num_pos) {
    __shared__ float s_warp[32];
    float local = 0.0f;
    for (int i = threadIdx.x; i < num_pos; i += blockDim.x) {
        float smrr = 1.0f / (float)(1 + g_cnt[i]);
        out[1 + i] = smrr;
        local += smrr;
    }
    // warp reduce
    for (int o = 16; o > 0; o >>= 1)
        local += __shfl_xor_sync(0xFFFFFFFFu, local, o);
    int lane = threadIdx.x & 31, wid = threadIdx.x >> 5;
    if (lane == 0) s_warp[wid] = local;
    __syncthreads();
    if (wid == 0) {
        int nw = (blockDim.x + 31) >> 5;
        float s = (lane < nw) ? s_warp[lane] : 0.0f;
        for (int o = 16; o > 0; o >>= 1)
            s += __shfl_xor_sync(0xFFFFFFFFu, s, o);
        if (lane == 0) out[0] = s / (float)num_pos;
    }
}

// ---------------------------------------------------------------------------
extern "C" void kernel_launch(void* const* d_in, const int* in_sizes, int n_in,
                              void* d_out, int out_size) {
    const float* val = (const float*)d_in[0];
    const int*   idx = (const int*)d_in[1];   // int32 (JAX x64 disabled)
    float* out = (float*)d_out;

    long long n_tot = (long long)in_sizes[0];

    int num_pos = out_size - 1;               // out = [mrr, sample_mrr(num_pos)]
    if (num_pos < 1) num_pos = 1;
    if (num_pos > POS_CAP) num_pos = POS_CAP;
    long long num_ll = n_tot / num_pos - 1;
    unsigned num = (num_ll > 0) ? (unsigned)num_ll : 1u;

    // Magic for division by num: p = (d * M) >> 42, exact for d < ~2^33.
    unsigned long long M = (4398046511104ULL / num) + 1ULL;  // 2^42

    long long n4 = n_tot / 4;

    // Pass A
    {
        int threads = 256;
        long long blocks = (n4 + threads - 1) / threads;
        if (blocks < 1) blocks = 1;
        passA_kernel<<<(unsigned)blocks, threads>>>(val, (const int4*)idx,
                                                    n4, n_tot, num_pos);
    }

    // Pass B (grid-stride, 32KB smem pos cache -> 7 blocks/SM)
    {
        int threads = 256;
        int blocks = 148 * 7;
        size_t smem = (size_t)num_pos * sizeof(float);
        passB_kernel<<<blocks, threads, smem>>>((const float4*)val,
                                                (const int4*)idx,
                                                n4, n_tot, num_pos, M);
    }

    // Finalize
    finalize_kernel<<<1, 1024>>>(out, num_pos);
}

// round 7
// speedup vs baseline: 7.3209x; 3.4942x over previous
#include <cuda_runtime.h>
#include <cstdint>

// Fixed problem shape: num_pos = 8192, num = 4000, N_TOT = 32,776,192.
#define POS_CAP   8192          // rows (num_pos)
#define WORDS_CAP (POS_CAP / 2) // u16-packed counter words
#define NBLK      592           // 148 SMs * 4 blocks
#define PB_THREADS 256

__device__ float        g_pos[POS_CAP];              // pos[j] values (32KB)
__device__ int          g_cnt[POS_CAP];              // final per-row counts
__device__ unsigned int g_part[(size_t)NBLK * WORDS_CAP]; // per-block tiles (9.7MB)

// ---------------------------------------------------------------------------
// Pass A: stream index (int32). Where j < num_pos, fetch val[i] into pos[j].
// Also zero the final counters.
__global__ void passA_kernel(const float* __restrict__ val,
                             const int4* __restrict__ idx4,
                             long long n4, long long n_tot, int num_pos) {
    long long t = (long long)blockIdx.x * blockDim.x + threadIdx.x;

    if (t < num_pos) g_cnt[t] = 0;

    if (t < n4) {
        int4 ii = idx4[t];
        long long base = 4 * t;
        if ((unsigned)ii.x < (unsigned)num_pos) g_pos[ii.x] = val[base + 0];
        if ((unsigned)ii.y < (unsigned)num_pos) g_pos[ii.y] = val[base + 1];
        if ((unsigned)ii.z < (unsigned)num_pos) g_pos[ii.z] = val[base + 2];
        if ((unsigned)ii.w < (unsigned)num_pos) g_pos[ii.w] = val[base + 3];
    }

    // Scalar tail (not hit for this shape).
    if (t == 0) {
        const int* idx = (const int*)idx4;
        for (long long i = 4 * n4; i < n_tot; i++) {
            int j = idx[i];
            if ((unsigned)j < (unsigned)num_pos) g_pos[j] = val[i];
        }
    }
}

// ---------------------------------------------------------------------------
// Pass B: stream val+idx. Negatives: p = (j - num_pos) * M >> 42 (magic div
// by num). Compare vs smem pos cache, count into u16-packed SMEM counters
// (ATOMS), then dump the block's tile with plain coalesced stores.
__global__ void __launch_bounds__(PB_THREADS)
passB_kernel(const float4* __restrict__ val4,
             const int4* __restrict__ idx4,
             long long n4, long long n_tot,
             int num_pos, unsigned long long M) {
    __shared__ float        s_pos[POS_CAP];   // 32KB
    __shared__ unsigned int s_cnt[WORDS_CAP]; // 16KB (2 x u16 rows per word)

    int words = (num_pos + 1) >> 1;
    for (int k = threadIdx.x; k < num_pos; k += blockDim.x)
        s_pos[k] = g_pos[k];
    for (int k = threadIdx.x; k < words; k += blockDim.x)
        s_cnt[k] = 0u;
    __syncthreads();

    long long stride = (long long)gridDim.x * blockDim.x;
    for (long long t = (long long)blockIdx.x * blockDim.x + threadIdx.x;
         t < n4; t += stride) {
        float4 v = val4[t];
        int4  ii = idx4[t];

        #define PROC(JJ, VV)                                                  \
        {                                                                     \
            if ((JJ) >= num_pos) {                                            \
                unsigned d = (unsigned)((JJ) - num_pos);                      \
                unsigned p = (unsigned)(((unsigned long long)d * M) >> 42);   \
                if ((VV) > s_pos[p])                                          \
                    atomicAdd(&s_cnt[p >> 1], 1u << ((p & 1u) << 4));         \
            }                                                                 \
        }
        PROC(ii.x, v.x)
        PROC(ii.y, v.y)
        PROC(ii.z, v.z)
        PROC(ii.w, v.w)
        #undef PROC
    }

    // Scalar tail (not hit for this shape).
    if (blockIdx.x == 0 && threadIdx.x == 0) {
        const float* val = (const float*)val4;
        const int*   idx = (const int*)idx4;
        for (long long i = 4 * n4; i < n_tot; i++) {
            int j = idx[i];
            if (j >= num_pos) {
                unsigned p = (unsigned)(((unsigned long long)(j - num_pos) * M) >> 42);
                if (val[i] > s_pos[p])
                    atomicAdd(&s_cnt[p >> 1], 1u << ((p & 1u) << 4));
            }
        }
    }
    __syncthreads();

    // Dump tile: plain coalesced stores, no atomics.
    size_t base = (size_t)blockIdx.x * words;
    for (int w = threadIdx.x; w < words; w += blockDim.x)
        g_part[base + w] = s_cnt[w];
}

// ---------------------------------------------------------------------------
// Reduce: sum NBLK tiles into g_cnt. CH chunks per word; 64K well-spread
// atomics total. Tiles are L2-resident (just written).
#define RED_CH 8
__global__ void reduce_kernel(int words, int nblk, int num_pos) {
    int tid = blockIdx.x * blockDim.x + threadIdx.x;
    int total = words * RED_CH;
    if (tid >= total) return;
    int w = tid % words;
    int c = tid / words;
    int per = (nblk + RED_CH - 1) / RED_CH;
    int b0 = c * per;
    int b1 = b0 + per; if (b1 > nblk) b1 = nblk;

    unsigned lo = 0, hi = 0;
    for (int b = b0; b < b1; b++) {
        unsigned x = g_part[(size_t)b * words + w];
        lo += x & 0xFFFFu;
        hi += x >> 16;
    }
    atomicAdd(&g_cnt[2 * w], (int)lo);
    if (2 * w + 1 < num_pos) atomicAdd(&g_cnt[2 * w + 1], (int)hi);
}

// ---------------------------------------------------------------------------
// Finalize: smrr = 1/(1+cnt), out[0] = mean, out[1..] = smrr. One block.
__global__ void finalize_kernel(float* __restrict__ out, int num_pos) {
    __shared__ float s_warp[32];
    float local = 0.0f;
    for (int i = threadIdx.x; i < num_pos; i += blockDim.x) {
        float smrr = 1.0f / (float)(1 + g_cnt[i]);
        out[1 + i] = smrr;
        local += smrr;
    }
    for (int o = 16; o > 0; o >>= 1)
        local += __shfl_xor_sync(0xFFFFFFFFu, local, o);
    int lane = threadIdx.x & 31, wid = threadIdx.x >> 5;
    if (lane == 0) s_warp[wid] = local;
    __syncthreads();
    if (wid == 0) {
        int nw = (blockDim.x + 31) >> 5;
        float s = (lane < nw) ? s_warp[lane] : 0.0f;
        for (int o = 16; o > 0; o >>= 1)
            s += __shfl_xor_sync(0xFFFFFFFFu, s, o);
        if (lane == 0) out[0] = s / (float)num_pos;
    }
}

// ---------------------------------------------------------------------------
extern "C" void kernel_launch(void* const* d_in, const int* in_sizes, int n_in,
                              void* d_out, int out_size) {
    const float* val = (const float*)d_in[0];
    const int*   idx = (const int*)d_in[1];   // int32 (JAX x64 disabled)
    float* out = (float*)d_out;

    long long n_tot = (long long)in_sizes[0];

    int num_pos = out_size - 1;               // out = [mrr, sample_mrr(num_pos)]
    if (num_pos < 1) num_pos = 1;
    if (num_pos > POS_CAP) num_pos = POS_CAP;
    long long num_ll = n_tot / num_pos - 1;
    unsigned num = (num_ll > 0) ? (unsigned)num_ll : 1u;

    // Magic for division by num: p = (d * M) >> 42, exact for this range.
    unsigned long long M = (4398046511104ULL / num) + 1ULL;  // 2^42

    long long n4 = n_tot / 4;
    int words = (num_pos + 1) >> 1;

    // Pass A
    {
        int threads = 256;
        long long blocks = (n4 + threads - 1) / threads;
        if (blocks < 1) blocks = 1;
        passA_kernel<<<(unsigned)blocks, threads>>>(val, (const int4*)idx,
                                                    n4, n_tot, num_pos);
    }

    // Pass B: fixed grid (4 blocks/SM), smem counters, no global atomics
    passB_kernel<<<NBLK, PB_THREADS>>>((const float4*)val, (const int4*)idx,
                                       n4, n_tot, num_pos, M);

    // Reduce tiles
    {
        int total = words * RED_CH;
        reduce_kernel<<<(total + 255) / 256, 256>>>(words, NBLK, num_pos);
    }

    // Finalize
    finalize_kernel<<<1, 1024>>>(out, num_pos);
}